// round 3
// baseline (speedup 1.0000x reference)
#include <cuda_runtime.h>

#define NBLOCKS 888      // 148 SMs x 6 resident blocks @ 40 regs/thread -> one full wave
#define NTHREADS 256

// Scratch via __device__ globals (no allocs allowed).
__device__ float        g_partial[NBLOCKS];
__device__ unsigned int g_count;   // zero-init at load; reset by last block each run

// 16 lanes cooperate on one row of D=64 floats (1 float4 per lane per tensor).
// 4-row unroll: 8 independent LDG.128 + 8 label LDGs in flight before shuffles.
__global__ void __launch_bounds__(NTHREADS)
speaker_loss_kernel(const int* __restrict__ s,
                    const float* __restrict__ vs,
                    const int* __restrict__ other_s,
                    const float* __restrict__ other_vs,
                    float* __restrict__ out, int B) {
    const int tid     = blockIdx.x * blockDim.x + threadIdx.x;
    const int group   = tid >> 4;
    const int lane16  = tid & 15;
    const int ngroups = (gridDim.x * blockDim.x) >> 4;
    const unsigned hmask = 0xFFFFu << (threadIdx.x & 16);

    float acc = 0.0f;

    int r = group;
    const int step4 = ngroups * 4;

    for (; r + 3 * ngroups < B; r += step4) {
        const int r0 = r, r1 = r + ngroups, r2 = r + 2 * ngroups, r3 = r + 3 * ngroups;

        const float4 x0 = __ldg(reinterpret_cast<const float4*>(vs + (size_t)r0 * 64) + lane16);
        const float4 x1 = __ldg(reinterpret_cast<const float4*>(vs + (size_t)r1 * 64) + lane16);
        const float4 x2 = __ldg(reinterpret_cast<const float4*>(vs + (size_t)r2 * 64) + lane16);
        const float4 x3 = __ldg(reinterpret_cast<const float4*>(vs + (size_t)r3 * 64) + lane16);
        const float4 y0 = __ldg(reinterpret_cast<const float4*>(other_vs + (size_t)r0 * 64) + lane16);
        const float4 y1 = __ldg(reinterpret_cast<const float4*>(other_vs + (size_t)r1 * 64) + lane16);
        const float4 y2 = __ldg(reinterpret_cast<const float4*>(other_vs + (size_t)r2 * 64) + lane16);
        const float4 y3 = __ldg(reinterpret_cast<const float4*>(other_vs + (size_t)r3 * 64) + lane16);

        // Labels in flight alongside the vector loads (used only by lane 0).
        int sa0 = 0, sa1 = 0, sa2 = 0, sa3 = 0, sb0 = 0, sb1 = 0, sb2 = 0, sb3 = 0;
        if (lane16 == 0) {
            sa0 = __ldg(&s[r0]); sb0 = __ldg(&other_s[r0]);
            sa1 = __ldg(&s[r1]); sb1 = __ldg(&other_s[r1]);
            sa2 = __ldg(&s[r2]); sb2 = __ldg(&other_s[r2]);
            sa3 = __ldg(&s[r3]); sb3 = __ldg(&other_s[r3]);
        }

        float d0x = x0.x - y0.x, d0y = x0.y - y0.y, d0z = x0.z - y0.z, d0w = x0.w - y0.w;
        float d1x = x1.x - y1.x, d1y = x1.y - y1.y, d1z = x1.z - y1.z, d1w = x1.w - y1.w;
        float d2x = x2.x - y2.x, d2y = x2.y - y2.y, d2z = x2.z - y2.z, d2w = x2.w - y2.w;
        float d3x = x3.x - y3.x, d3y = x3.y - y3.y, d3z = x3.z - y3.z, d3w = x3.w - y3.w;

        float p0 = d0x * d0x + d0y * d0y + d0z * d0z + d0w * d0w;
        float p1 = d1x * d1x + d1y * d1y + d1z * d1z + d1w * d1w;
        float p2 = d2x * d2x + d2y * d2y + d2z * d2z + d2w * d2w;
        float p3 = d3x * d3x + d3y * d3y + d3z * d3z + d3w * d3w;

        #pragma unroll
        for (int off = 8; off > 0; off >>= 1) {
            p0 += __shfl_xor_sync(hmask, p0, off);
            p1 += __shfl_xor_sync(hmask, p1, off);
            p2 += __shfl_xor_sync(hmask, p2, off);
            p3 += __shfl_xor_sync(hmask, p3, off);
        }

        if (lane16 == 0) {
            float v0 = (sa0 != sb0) ? fmaxf(1.0f - p0, 0.0f) : p0;
            float v1 = (sa1 != sb1) ? fmaxf(1.0f - p1, 0.0f) : p1;
            float v2 = (sa2 != sb2) ? fmaxf(1.0f - p2, 0.0f) : p2;
            float v3 = (sa3 != sb3) ? fmaxf(1.0f - p3, 0.0f) : p3;
            acc += (v0 + v1) + (v2 + v3);
        }
    }

    // Tail (<=3 rows per group).
    for (; r < B; r += ngroups) {
        const float4 x = __ldg(reinterpret_cast<const float4*>(vs + (size_t)r * 64) + lane16);
        const float4 y = __ldg(reinterpret_cast<const float4*>(other_vs + (size_t)r * 64) + lane16);
        float dx = x.x - y.x, dy = x.y - y.y, dz = x.z - y.z, dw = x.w - y.w;
        float p = dx * dx + dy * dy + dz * dz + dw * dw;
        #pragma unroll
        for (int off = 8; off > 0; off >>= 1)
            p += __shfl_xor_sync(hmask, p, off);
        if (lane16 == 0) {
            if (__ldg(&s[r]) != __ldg(&other_s[r])) p = fmaxf(1.0f - p, 0.0f);
            acc += p;
        }
    }

    // ---- Block reduction ----
    #pragma unroll
    for (int off = 16; off > 0; off >>= 1)
        acc += __shfl_xor_sync(0xFFFFFFFFu, acc, off);

    __shared__ float warpsum[NTHREADS / 32];
    __shared__ bool  is_last;
    const int wid = threadIdx.x >> 5;
    const int lid = threadIdx.x & 31;
    if (lid == 0) warpsum[wid] = acc;
    __syncthreads();

    if (threadIdx.x == 0) {
        float bsum = 0.0f;
        #pragma unroll
        for (int i = 0; i < NTHREADS / 32; i++) bsum += warpsum[i];
        g_partial[blockIdx.x] = bsum;
        __threadfence();
        unsigned int prev = atomicAdd(&g_count, 1u);
        is_last = (prev == gridDim.x - 1);
    }
    __syncthreads();

    // ---- Last block finalizes: reduce partials, write out, reset counter ----
    if (is_last) {
        double v = 0.0;
        for (int i = threadIdx.x; i < (int)gridDim.x; i += blockDim.x)
            v += (double)g_partial[i];
        #pragma unroll
        for (int off = 16; off > 0; off >>= 1) {
            double o = __longlong_as_double(
                __shfl_xor_sync(0xFFFFFFFFu, __double_as_longlong(v), off));
            v += o;
        }
        __shared__ double wsum2[NTHREADS / 32];
        if (lid == 0) wsum2[wid] = v;
        __syncthreads();
        if (threadIdx.x == 0) {
            double t = 0.0;
            #pragma unroll
            for (int i = 0; i < NTHREADS / 32; i++) t += wsum2[i];
            out[0] = (float)(t / (double)B);
            g_count = 0;   // reset for next graph replay
        }
    }
}

extern "C" void kernel_launch(void* const* d_in, const int* in_sizes, int n_in,
                              void* d_out, int out_size) {
    const int*   s        = (const int*)d_in[0];
    const float* vs       = (const float*)d_in[1];
    const int*   other_s  = (const int*)d_in[2];
    const float* other_vs = (const float*)d_in[3];
    float*       out      = (float*)d_out;

    const int B = in_sizes[0];

    speaker_loss_kernel<<<NBLOCKS, NTHREADS>>>(s, vs, other_s, other_vs, out, B);
}

// round 4
// speedup vs baseline: 1.2070x; 1.2070x over previous
#include <cuda_runtime.h>

#define NBLOCKS 888      // 148 SMs x 6 resident blocks -> exactly ONE wave
#define NTHREADS 256

// Scratch via __device__ globals (no allocs allowed).
__device__ float        g_partial[NBLOCKS];
__device__ unsigned int g_count;   // zero-init at load; reset by last block each run

// 16 lanes cooperate on one row of D=64 floats (1 float4 per lane per tensor).
// 4-row unroll: 8 independent LDG.128 in flight before the shuffle chains.
// __launch_bounds__(256, 6) pins regs <= 42 so 6 blocks/SM actually fit.
__global__ void __launch_bounds__(NTHREADS, 6)
speaker_loss_kernel(const int* __restrict__ s,
                    const float* __restrict__ vs,
                    const int* __restrict__ other_s,
                    const float* __restrict__ other_vs,
                    float* __restrict__ out, int B) {
    const int tid     = blockIdx.x * blockDim.x + threadIdx.x;
    const int group   = tid >> 4;
    const int lane16  = tid & 15;
    const int ngroups = (gridDim.x * blockDim.x) >> 4;
    const unsigned hmask = 0xFFFFu << (threadIdx.x & 16);

    float acc = 0.0f;

    int r = group;
    const int step4 = ngroups * 4;

    for (; r + 3 * ngroups < B; r += step4) {
        const int r0 = r, r1 = r + ngroups, r2 = r + 2 * ngroups, r3 = r + 3 * ngroups;

        const float4 x0 = __ldg(reinterpret_cast<const float4*>(vs + (size_t)r0 * 64) + lane16);
        const float4 x1 = __ldg(reinterpret_cast<const float4*>(vs + (size_t)r1 * 64) + lane16);
        const float4 x2 = __ldg(reinterpret_cast<const float4*>(vs + (size_t)r2 * 64) + lane16);
        const float4 x3 = __ldg(reinterpret_cast<const float4*>(vs + (size_t)r3 * 64) + lane16);
        const float4 y0 = __ldg(reinterpret_cast<const float4*>(other_vs + (size_t)r0 * 64) + lane16);
        const float4 y1 = __ldg(reinterpret_cast<const float4*>(other_vs + (size_t)r1 * 64) + lane16);
        const float4 y2 = __ldg(reinterpret_cast<const float4*>(other_vs + (size_t)r2 * 64) + lane16);
        const float4 y3 = __ldg(reinterpret_cast<const float4*>(other_vs + (size_t)r3 * 64) + lane16);

        float d0x = x0.x - y0.x, d0y = x0.y - y0.y, d0z = x0.z - y0.z, d0w = x0.w - y0.w;
        float d1x = x1.x - y1.x, d1y = x1.y - y1.y, d1z = x1.z - y1.z, d1w = x1.w - y1.w;
        float d2x = x2.x - y2.x, d2y = x2.y - y2.y, d2z = x2.z - y2.z, d2w = x2.w - y2.w;
        float d3x = x3.x - y3.x, d3y = x3.y - y3.y, d3z = x3.z - y3.z, d3w = x3.w - y3.w;

        float p0 = d0x * d0x + d0y * d0y + d0z * d0z + d0w * d0w;
        float p1 = d1x * d1x + d1y * d1y + d1z * d1z + d1w * d1w;
        float p2 = d2x * d2x + d2y * d2y + d2z * d2z + d2w * d2w;
        float p3 = d3x * d3x + d3y * d3y + d3z * d3z + d3w * d3w;

        #pragma unroll
        for (int off = 8; off > 0; off >>= 1) {
            p0 += __shfl_xor_sync(hmask, p0, off);
            p1 += __shfl_xor_sync(hmask, p1, off);
            p2 += __shfl_xor_sync(hmask, p2, off);
            p3 += __shfl_xor_sync(hmask, p3, off);
        }

        if (lane16 == 0) {
            float v0 = (__ldg(&s[r0]) != __ldg(&other_s[r0])) ? fmaxf(1.0f - p0, 0.0f) : p0;
            float v1 = (__ldg(&s[r1]) != __ldg(&other_s[r1])) ? fmaxf(1.0f - p1, 0.0f) : p1;
            float v2 = (__ldg(&s[r2]) != __ldg(&other_s[r2])) ? fmaxf(1.0f - p2, 0.0f) : p2;
            float v3 = (__ldg(&s[r3]) != __ldg(&other_s[r3])) ? fmaxf(1.0f - p3, 0.0f) : p3;
            acc += (v0 + v1) + (v2 + v3);
        }
    }

    // Tail (<=3 rows per group).
    for (; r < B; r += ngroups) {
        const float4 x = __ldg(reinterpret_cast<const float4*>(vs + (size_t)r * 64) + lane16);
        const float4 y = __ldg(reinterpret_cast<const float4*>(other_vs + (size_t)r * 64) + lane16);
        float dx = x.x - y.x, dy = x.y - y.y, dz = x.z - y.z, dw = x.w - y.w;
        float p = dx * dx + dy * dy + dz * dz + dw * dw;
        #pragma unroll
        for (int off = 8; off > 0; off >>= 1)
            p += __shfl_xor_sync(hmask, p, off);
        if (lane16 == 0) {
            if (__ldg(&s[r]) != __ldg(&other_s[r])) p = fmaxf(1.0f - p, 0.0f);
            acc += p;
        }
    }

    // ---- Block reduction ----
    #pragma unroll
    for (int off = 16; off > 0; off >>= 1)
        acc += __shfl_xor_sync(0xFFFFFFFFu, acc, off);

    __shared__ float warpsum[NTHREADS / 32];
    __shared__ bool  is_last;
    const int wid = threadIdx.x >> 5;
    const int lid = threadIdx.x & 31;
    if (lid == 0) warpsum[wid] = acc;
    __syncthreads();

    if (threadIdx.x == 0) {
        float bsum = 0.0f;
        #pragma unroll
        for (int i = 0; i < NTHREADS / 32; i++) bsum += warpsum[i];
        g_partial[blockIdx.x] = bsum;
        __threadfence();
        unsigned int prev = atomicAdd(&g_count, 1u);
        is_last = (prev == gridDim.x - 1);
    }
    __syncthreads();

    // ---- Last block finalizes: reduce partials, write out, reset counter ----
    if (is_last) {
        double v = 0.0;
        for (int i = threadIdx.x; i < (int)gridDim.x; i += blockDim.x)
            v += (double)g_partial[i];
        #pragma unroll
        for (int off = 16; off > 0; off >>= 1) {
            double o = __longlong_as_double(
                __shfl_xor_sync(0xFFFFFFFFu, __double_as_longlong(v), off));
            v += o;
        }
        __shared__ double wsum2[NTHREADS / 32];
        if (lid == 0) wsum2[wid] = v;
        __syncthreads();
        if (threadIdx.x == 0) {
            double t = 0.0;
            #pragma unroll
            for (int i = 0; i < NTHREADS / 32; i++) t += wsum2[i];
            out[0] = (float)(t / (double)B);
            g_count = 0;   // reset for next graph replay
        }
    }
}

extern "C" void kernel_launch(void* const* d_in, const int* in_sizes, int n_in,
                              void* d_out, int out_size) {
    const int*   s        = (const int*)d_in[0];
    const float* vs       = (const float*)d_in[1];
    const int*   other_s  = (const int*)d_in[2];
    const float* other_vs = (const float*)d_in[3];
    float*       out      = (float*)d_out;

    const int B = in_sizes[0];

    speaker_loss_kernel<<<NBLOCKS, NTHREADS>>>(s, vs, other_s, other_vs, out, B);
}

// round 5
// speedup vs baseline: 1.2080x; 1.0008x over previous
#include <cuda_runtime.h>

#define NBLOCKS 1184     // 148 SMs x 8 resident blocks -> exactly ONE wave @ 32 regs
#define NTHREADS 256

// Scratch via __device__ globals (no allocs allowed).
__device__ float        g_partial[NBLOCKS];
__device__ unsigned int g_count;   // zero-init at load; reset by last block each run

// 16 lanes cooperate on one row of D=64 floats (1 float4 per lane per tensor).
// 2-row unroll (4 live float4 staging regs) so the body fits in 32 regs and
// 8 blocks/SM are resident: latency hiding via 64 warps/SM instead of deep ILP.
__global__ void __launch_bounds__(NTHREADS, 8)
speaker_loss_kernel(const int* __restrict__ s,
                    const float* __restrict__ vs,
                    const int* __restrict__ other_s,
                    const float* __restrict__ other_vs,
                    float* __restrict__ out, int B) {
    const int tid     = blockIdx.x * blockDim.x + threadIdx.x;
    const int group   = tid >> 4;
    const int lane16  = tid & 15;
    const int ngroups = (gridDim.x * blockDim.x) >> 4;
    const unsigned hmask = 0xFFFFu << (threadIdx.x & 16);

    float acc = 0.0f;

    int r = group;
    const int step2 = ngroups * 2;

    for (; r + ngroups < B; r += step2) {
        const int r0 = r, r1 = r + ngroups;

        const float4 x0 = __ldg(reinterpret_cast<const float4*>(vs + (size_t)r0 * 64) + lane16);
        const float4 x1 = __ldg(reinterpret_cast<const float4*>(vs + (size_t)r1 * 64) + lane16);
        const float4 y0 = __ldg(reinterpret_cast<const float4*>(other_vs + (size_t)r0 * 64) + lane16);
        const float4 y1 = __ldg(reinterpret_cast<const float4*>(other_vs + (size_t)r1 * 64) + lane16);

        float d0x = x0.x - y0.x, d0y = x0.y - y0.y, d0z = x0.z - y0.z, d0w = x0.w - y0.w;
        float d1x = x1.x - y1.x, d1y = x1.y - y1.y, d1z = x1.z - y1.z, d1w = x1.w - y1.w;

        float p0 = d0x * d0x + d0y * d0y + d0z * d0z + d0w * d0w;
        float p1 = d1x * d1x + d1y * d1y + d1z * d1z + d1w * d1w;

        #pragma unroll
        for (int off = 8; off > 0; off >>= 1) {
            p0 += __shfl_xor_sync(hmask, p0, off);
            p1 += __shfl_xor_sync(hmask, p1, off);
        }

        if (lane16 == 0) {
            float v0 = (__ldg(&s[r0]) != __ldg(&other_s[r0])) ? fmaxf(1.0f - p0, 0.0f) : p0;
            float v1 = (__ldg(&s[r1]) != __ldg(&other_s[r1])) ? fmaxf(1.0f - p1, 0.0f) : p1;
            acc += v0 + v1;
        }
    }

    // Tail (<=1 row per group).
    for (; r < B; r += ngroups) {
        const float4 x = __ldg(reinterpret_cast<const float4*>(vs + (size_t)r * 64) + lane16);
        const float4 y = __ldg(reinterpret_cast<const float4*>(other_vs + (size_t)r * 64) + lane16);
        float dx = x.x - y.x, dy = x.y - y.y, dz = x.z - y.z, dw = x.w - y.w;
        float p = dx * dx + dy * dy + dz * dz + dw * dw;
        #pragma unroll
        for (int off = 8; off > 0; off >>= 1)
            p += __shfl_xor_sync(hmask, p, off);
        if (lane16 == 0) {
            if (__ldg(&s[r]) != __ldg(&other_s[r])) p = fmaxf(1.0f - p, 0.0f);
            acc += p;
        }
    }

    // ---- Block reduction ----
    #pragma unroll
    for (int off = 16; off > 0; off >>= 1)
        acc += __shfl_xor_sync(0xFFFFFFFFu, acc, off);

    __shared__ float warpsum[NTHREADS / 32];
    __shared__ bool  is_last;
    const int wid = threadIdx.x >> 5;
    const int lid = threadIdx.x & 31;
    if (lid == 0) warpsum[wid] = acc;
    __syncthreads();

    if (threadIdx.x == 0) {
        float bsum = 0.0f;
        #pragma unroll
        for (int i = 0; i < NTHREADS / 32; i++) bsum += warpsum[i];
        g_partial[blockIdx.x] = bsum;
        __threadfence();
        unsigned int prev = atomicAdd(&g_count, 1u);
        is_last = (prev == gridDim.x - 1);
    }
    __syncthreads();

    // ---- Last block finalizes: reduce partials, write out, reset counter ----
    if (is_last) {
        double v = 0.0;
        for (int i = threadIdx.x; i < (int)gridDim.x; i += blockDim.x)
            v += (double)g_partial[i];
        #pragma unroll
        for (int off = 16; off > 0; off >>= 1) {
            double o = __longlong_as_double(
                __shfl_xor_sync(0xFFFFFFFFu, __double_as_longlong(v), off));
            v += o;
        }
        __shared__ double wsum2[NTHREADS / 32];
        if (lid == 0) wsum2[wid] = v;
        __syncthreads();
        if (threadIdx.x == 0) {
            double t = 0.0;
            #pragma unroll
            for (int i = 0; i < NTHREADS / 32; i++) t += wsum2[i];
            out[0] = (float)(t / (double)B);
            g_count = 0;   // reset for next graph replay
        }
    }
}

extern "C" void kernel_launch(void* const* d_in, const int* in_sizes, int n_in,
                              void* d_out, int out_size) {
    const int*   s        = (const int*)d_in[0];
    const float* vs       = (const float*)d_in[1];
    const int*   other_s  = (const int*)d_in[2];
    const float* other_vs = (const float*)d_in[3];
    float*       out      = (float*)d_out;

    const int B = in_sizes[0];

    speaker_loss_kernel<<<NBLOCKS, NTHREADS>>>(s, vs, other_s, other_vs, out, B);
}